// round 3
// baseline (speedup 1.0000x reference)
#include <cuda_runtime.h>
#include <cuda_bf16.h>

#define N_NODES 1024
#define D_EMB 64
#define F_IN 128
#define H_DIM 64
#define N_CLS 8

// Scratch (no cudaMalloc allowed)
__device__ float g_a[N_NODES * H_DIM];     // embed @ W1[:64] + b1
__device__ float g_b[N_NODES * H_DIM];     // embed @ W1[64:]
__device__ float g_xw[N_NODES * H_DIM];    // x @ Wg1
__device__ float g_gate[N_NODES * N_NODES];
__device__ float g_pool[H_DIM];            // sum over nodes of relu(M @ xw)

// ---------------------------------------------------------------------------
// Kernel 1: per-node precompute. 128 blocks x 64 threads, 8 rows per block.
// Block 0 also zeroes g_pool (consumed by spmm_kernel later in the stream).
// ---------------------------------------------------------------------------
__global__ __launch_bounds__(64) void prep_kernel(
    const float* __restrict__ embed, const float* __restrict__ x,
    const float* __restrict__ W1, const float* __restrict__ b1,
    const float* __restrict__ Wg1)
{
    __shared__ float se[8 * D_EMB];
    __shared__ float sx[8 * F_IN];
    const int t = threadIdx.x;            // 0..63 = output column
    const int i0 = blockIdx.x * 8;

    if (blockIdx.x == 0) g_pool[t] = 0.f;

    #pragma unroll
    for (int p = 0; p < 8; p++)  se[t + p * 64] = embed[i0 * D_EMB + t + p * 64];
    #pragma unroll
    for (int p = 0; p < 16; p++) sx[t + p * 64] = x[i0 * F_IN + t + p * 64];
    __syncthreads();

    float va[8], vb[8], vx[8];
    const float bias = b1[t];
    #pragma unroll
    for (int r = 0; r < 8; r++) { va[r] = bias; vb[r] = 0.f; vx[r] = 0.f; }

    #pragma unroll 4
    for (int k = 0; k < D_EMB; k++) {
        const float w1a = W1[k * H_DIM + t];
        const float w1b = W1[(D_EMB + k) * H_DIM + t];
        #pragma unroll
        for (int r = 0; r < 8; r++) {
            const float e = se[r * D_EMB + k];
            va[r] = fmaf(e, w1a, va[r]);
            vb[r] = fmaf(e, w1b, vb[r]);
        }
    }
    #pragma unroll 4
    for (int k = 0; k < F_IN; k++) {
        const float wg = Wg1[k * H_DIM + t];
        #pragma unroll
        for (int r = 0; r < 8; r++)
            vx[r] = fmaf(sx[r * F_IN + k], wg, vx[r]);
    }
    #pragma unroll
    for (int r = 0; r < 8; r++) {
        g_a [(i0 + r) * H_DIM + t] = va[r];
        g_b [(i0 + r) * H_DIM + t] = vb[r];
        g_xw[(i0 + r) * H_DIM + t] = vx[r];
    }
}

// ---------------------------------------------------------------------------
// Kernel 2: per-edge gate. Grid (16,16), block 256; each block = 64x64 edges,
// each thread a 4x4 micro-tile. smem stored transposed [k][row], pad 68
// (float4-aligned; inner-loop LDS.128 conflict-free).
// ---------------------------------------------------------------------------
__device__ __forceinline__ float gate_of(float u, float la, float invb)
{
    // sigmoid((log(u) - log(1-u) + la) / beta)
    const float z = (__logf(u) - __logf(1.f - u) + la) * invb;
    return __frcp_rn(1.f + __expf(-z));
}

__global__ __launch_bounds__(256) void edge_kernel(
    const float* __restrict__ noise, const float* __restrict__ W2,
    const float* __restrict__ b2, const float* __restrict__ tmp)
{
    __shared__ __align__(16) float sa[64 * 68];
    __shared__ __align__(16) float sb[64 * 68];
    __shared__ float sw2[64];

    const int t  = threadIdx.x;
    const int i0 = blockIdx.y * 64;
    const int j0 = blockIdx.x * 64;

    // load 64 rows x 64 cols of g_a / g_b, transposed into [k][r]
    #pragma unroll
    for (int p = 0; p < 16; p++) {
        const int idx = t + p * 256;
        const int r = idx >> 6;          // 0..63
        const int k = idx & 63;          // 0..63
        sa[k * 68 + r] = g_a[(i0 + r) * H_DIM + k];
        sb[k * 68 + r] = g_b[(j0 + r) * H_DIM + k];
    }
    if (t < 64) sw2[t] = W2[t];
    __syncthreads();

    const int tx = t & 15, ty = t >> 4;   // 16 x 16 threads, 4x4 each
    const float b2s = b2[0];
    float acc[4][4];
    #pragma unroll
    for (int r = 0; r < 4; r++)
        #pragma unroll
        for (int c = 0; c < 4; c++) acc[r][c] = b2s;

    #pragma unroll 4
    for (int k = 0; k < 64; k++) {
        const float4 ra = *(const float4*)&sa[k * 68 + 4 * ty];
        const float4 rb = *(const float4*)&sb[k * 68 + 4 * tx];
        const float w = sw2[k];
        const float av[4] = {ra.x, ra.y, ra.z, ra.w};
        const float bv[4] = {rb.x, rb.y, rb.z, rb.w};
        #pragma unroll
        for (int r = 0; r < 4; r++)
            #pragma unroll
            for (int c = 0; c < 4; c++)
                acc[r][c] = fmaf(fmaxf(av[r] + bv[c], 0.f), w, acc[r][c]);
    }

    const float invb = __frcp_rn(tmp[0]);
    const int j = j0 + 4 * tx;
    #pragma unroll
    for (int r = 0; r < 4; r++) {
        const int i = i0 + 4 * ty + r;
        const float4 u = *(const float4*)&noise[(size_t)i * N_NODES + j];
        float4 o;
        o.x = gate_of(u.x, acc[r][0], invb);
        o.y = gate_of(u.y, acc[r][1], invb);
        o.z = gate_of(u.z, acc[r][2], invb);
        o.w = gate_of(u.w, acc[r][3], invb);
        *(float4*)&g_gate[(size_t)i * N_NODES + j] = o;
    }
}

// ---------------------------------------------------------------------------
// Kernel 3: pool += sum_rows relu( (adj .* 0.5*(G+G^T)) @ xw ).
// 128 blocks x 256 thr; each block owns 8 rows, k tiled by 64.
// Mean-pool fused: block-local smem reduction + 64 atomicAdds.
// ---------------------------------------------------------------------------
__global__ __launch_bounds__(256) void spmm_kernel(const float* __restrict__ adj)
{
    __shared__ float s_ah[8 * 64];                  // 0.5 * adj tile
    __shared__ float s_m [8 * 64];                  // masked-adj tile
    __shared__ __align__(16) float s_xw[64 * 64];   // xw k-tile
    __shared__ float s_red[8 * 64];                 // per-row relu results

    const int t  = threadIdx.x;
    const int i0 = blockIdx.x * 8;
    const int f2 = (t & 31) * 2;     // 2 adjacent output cols
    const int rr = t >> 5;           // row 0..7

    float acc0 = 0.f, acc1 = 0.f;

    for (int k0 = 0; k0 < N_NODES; k0 += 64) {
        __syncthreads();
        // adj + forward-gate part of mask, and xw tile
        #pragma unroll
        for (int p = 0; p < 2; p++) {
            const int idx = t + p * 256;
            const int r = idx >> 6, k = idx & 63;
            const float av = 0.5f * adj[(size_t)(i0 + r) * N_NODES + k0 + k];
            s_ah[r * 64 + k] = av;
            s_m [r * 64 + k] = av * g_gate[(size_t)(i0 + r) * N_NODES + k0 + k];
        }
        #pragma unroll
        for (int p = 0; p < 16; p++) {
            const int idx = t + p * 256;
            const int k = idx >> 6, f = idx & 63;
            s_xw[k * 64 + f] = g_xw[(k0 + k) * H_DIM + f];
        }
        __syncthreads();
        // transposed-gate part: G[k][i]
        #pragma unroll
        for (int p = 0; p < 2; p++) {
            const int idx = t + p * 256;
            const int k = idx >> 3, r = idx & 7;
            s_m[r * 64 + k] += s_ah[r * 64 + k] *
                               g_gate[(size_t)(k0 + k) * N_NODES + i0 + r];
        }
        __syncthreads();

        #pragma unroll
        for (int k = 0; k < 64; k++) {
            const float mv  = s_m[rr * 64 + k];
            const float2 xv = *(const float2*)&s_xw[k * 64 + f2];
            acc0 = fmaf(mv, xv.x, acc0);
            acc1 = fmaf(mv, xv.y, acc1);
        }
    }
    s_red[rr * 64 + f2]     = fmaxf(acc0, 0.f);
    s_red[rr * 64 + f2 + 1] = fmaxf(acc1, 0.f);
    __syncthreads();
    if (t < 64) {
        float s = 0.f;
        #pragma unroll
        for (int r = 0; r < 8; r++) s += s_red[r * 64 + t];
        atomicAdd(&g_pool[t], s);
    }
}

// ---------------------------------------------------------------------------
// Kernel 4: logits + softmax on the 64-wide pooled vector. One tiny block.
// ---------------------------------------------------------------------------
__global__ __launch_bounds__(64) void final_kernel(
    const float* __restrict__ Wg2, float* __restrict__ out)
{
    __shared__ float sp[64];
    __shared__ float slog[8];
    __shared__ float sexp[8];

    const int t = threadIdx.x;
    sp[t] = g_pool[t] * (1.0f / (float)N_NODES);
    __syncthreads();
    if (t < N_CLS) {
        float lg = 0.f;
        #pragma unroll 8
        for (int k = 0; k < 64; k++) lg += sp[k] * Wg2[k * N_CLS + t];
        slog[t] = lg;
    }
    __syncthreads();
    if (t < N_CLS) {
        float m = slog[0];
        #pragma unroll
        for (int cc = 1; cc < N_CLS; cc++) m = fmaxf(m, slog[cc]);
        sexp[t] = expf(slog[t] - m);
    }
    __syncthreads();
    if (t < N_CLS) {
        float sum = 0.f;
        #pragma unroll
        for (int cc = 0; cc < N_CLS; cc++) sum += sexp[cc];
        out[t] = sexp[t] / sum;
    }
}

// ---------------------------------------------------------------------------
extern "C" void kernel_launch(void* const* d_in, const int* in_sizes, int n_in,
                              void* d_out, int out_size)
{
    const float* x     = (const float*)d_in[0];
    const float* embed = (const float*)d_in[1];
    const float* adj   = (const float*)d_in[2];
    const float* tmp   = (const float*)d_in[3];
    const float* noise = (const float*)d_in[4];
    // d_in[5] = label (int), unused by the forward pass
    const float* W1    = (const float*)d_in[6];
    const float* b1    = (const float*)d_in[7];
    const float* W2    = (const float*)d_in[8];
    const float* b2    = (const float*)d_in[9];
    const float* Wg1   = (const float*)d_in[10];
    const float* Wg2   = (const float*)d_in[11];
    float* out = (float*)d_out;

    prep_kernel<<<128, 64>>>(embed, x, W1, b1, Wg1);
    edge_kernel<<<dim3(16, 16), 256>>>(noise, W2, b2, tmp);
    spmm_kernel<<<128, 256>>>(adj);
    final_kernel<<<1, 64>>>(Wg2, out);
}

// round 5
// speedup vs baseline: 1.0088x; 1.0088x over previous
#include <cuda_runtime.h>
#include <cuda_bf16.h>

#define N_NODES 1024
#define D_EMB 64
#define F_IN 128
#define H_DIM 64
#define N_CLS 8
#define EPAD 68
#define NBLK 16   // 1024/64 node blocks

// Scratch (no cudaMalloc allowed)
__device__ float g_a[N_NODES * H_DIM];     // embed @ W1[:64] + b1
__device__ float g_b[N_NODES * H_DIM];     // embed @ W1[64:]
__device__ float g_xw[N_NODES * H_DIM];    // x @ Wg1
__device__ float g_m[N_NODES * N_NODES];   // masked_adj = adj .* sym_mask
__device__ float g_pool[H_DIM];            // sum over nodes of relu(m @ xw)

// ---------------------------------------------------------------------------
// Kernel 1: per-node precompute. 128 blocks x 64 threads, 8 rows per block.
// ---------------------------------------------------------------------------
__global__ __launch_bounds__(64) void prep_kernel(
    const float* __restrict__ embed, const float* __restrict__ x,
    const float* __restrict__ W1, const float* __restrict__ b1,
    const float* __restrict__ Wg1)
{
    __shared__ float se[8 * D_EMB];
    __shared__ float sx[8 * F_IN];
    const int t = threadIdx.x;            // 0..63 = output column
    const int i0 = blockIdx.x * 8;

    if (blockIdx.x == 0) g_pool[t] = 0.f;

    #pragma unroll
    for (int p = 0; p < 8; p++)  se[t + p * 64] = embed[i0 * D_EMB + t + p * 64];
    #pragma unroll
    for (int p = 0; p < 16; p++) sx[t + p * 64] = x[i0 * F_IN + t + p * 64];
    __syncthreads();

    float va[8], vb[8], vx[8];
    const float bias = b1[t];
    #pragma unroll
    for (int r = 0; r < 8; r++) { va[r] = bias; vb[r] = 0.f; vx[r] = 0.f; }

    #pragma unroll 4
    for (int k = 0; k < D_EMB; k++) {
        const float w1a = W1[k * H_DIM + t];
        const float w1b = W1[(D_EMB + k) * H_DIM + t];
        #pragma unroll
        for (int r = 0; r < 8; r++) {
            const float e = se[r * D_EMB + k];
            va[r] = fmaf(e, w1a, va[r]);
            vb[r] = fmaf(e, w1b, vb[r]);
        }
    }
    #pragma unroll 4
    for (int k = 0; k < F_IN; k++) {
        const float wg = Wg1[k * H_DIM + t];
        #pragma unroll
        for (int r = 0; r < 8; r++)
            vx[r] = fmaf(sx[r * F_IN + k], wg, vx[r]);
    }
    #pragma unroll
    for (int r = 0; r < 8; r++) {
        g_a [(i0 + r) * H_DIM + t] = va[r];
        g_b [(i0 + r) * H_DIM + t] = vb[r];
        g_xw[(i0 + r) * H_DIM + t] = vx[r];
    }
}

// ---------------------------------------------------------------------------
// Kernel 2: symmetric edge gate -> masked_adj directly.
// 136 blocks (upper-triangle 64x64 block pairs) x 256 threads.
// Each thread: 4x4 tile of la(i,j) AND 4x4 of la(j,i); writes both mirror
// tiles of m = adj .* 0.5*(sigma(z_ij)+sigma(z_ji)). No transpose pass needed.
// ---------------------------------------------------------------------------
__device__ __forceinline__ float gate_of(float u, float la, float invb)
{
    const float z = (__logf(u) - __logf(1.f - u) + la) * invb;
    return __frcp_rn(1.f + __expf(-z));
}

extern __shared__ float smem_e[];

__global__ __launch_bounds__(256) void edge_kernel(
    const float* __restrict__ noise, const float* __restrict__ adj,
    const float* __restrict__ W2, const float* __restrict__ b2,
    const float* __restrict__ tmp)
{
    float* sAi = smem_e;                 // A^T rows of i-block  [64k x 68]
    float* sBj = sAi + 64 * EPAD;        // B^T rows of j-block
    float* sAj = sBj + 64 * EPAD;        // A^T rows of j-block
    float* sBi = sAj + 64 * EPAD;        // B^T rows of i-block
    float* sw2 = sBi + 64 * EPAD;

    const int t = threadIdx.x;
    // decode upper-triangle (bi <= bj)
    int b = blockIdx.x, bi = 0;
    while (b >= NBLK - bi) { b -= NBLK - bi; bi++; }
    const int bj = bi + b;
    const int i0 = bi * 64, j0 = bj * 64;

    #pragma unroll
    for (int p = 0; p < 16; p++) {
        const int idx = t + p * 256;
        const int r = idx >> 6, k = idx & 63;
        sAi[k * EPAD + r] = g_a[(i0 + r) * H_DIM + k];
        sBi[k * EPAD + r] = g_b[(i0 + r) * H_DIM + k];
        sAj[k * EPAD + r] = g_a[(j0 + r) * H_DIM + k];
        sBj[k * EPAD + r] = g_b[(j0 + r) * H_DIM + k];
    }
    if (t < 64) sw2[t] = W2[t];
    __syncthreads();

    const int tx = t & 15, ty = t >> 4;
    const float b2s = b2[0];
    float acc1[4][4], acc2[4][4];  // acc1[r][c]=la(I_r,J_c), acc2[c][r]=la(J_c,I_r)
    #pragma unroll
    for (int r = 0; r < 4; r++)
        #pragma unroll
        for (int c = 0; c < 4; c++) { acc1[r][c] = b2s; acc2[r][c] = b2s; }

    #pragma unroll 2
    for (int k = 0; k < 64; k++) {
        const float4 ai = *(const float4*)&sAi[k * EPAD + 4 * ty];
        const float4 bj4= *(const float4*)&sBj[k * EPAD + 4 * tx];
        const float4 aj = *(const float4*)&sAj[k * EPAD + 4 * tx];
        const float4 bi4= *(const float4*)&sBi[k * EPAD + 4 * ty];
        const float w = sw2[k];
        const float av1[4] = {ai.x, ai.y, ai.z, ai.w};
        const float bv1[4] = {bj4.x, bj4.y, bj4.z, bj4.w};
        const float av2[4] = {aj.x, aj.y, aj.z, aj.w};
        const float bv2[4] = {bi4.x, bi4.y, bi4.z, bi4.w};
        #pragma unroll
        for (int r = 0; r < 4; r++)
            #pragma unroll
            for (int c = 0; c < 4; c++) {
                acc1[r][c] = fmaf(fmaxf(av1[r] + bv1[c], 0.f), w, acc1[r][c]);
                acc2[c][r] = fmaf(fmaxf(av2[c] + bv2[r], 0.f), w, acc2[c][r]);
            }
    }

    const float invb = __frcp_rn(tmp[0]);
    float g1[4][4], g2[4][4];   // g1[r][c]=gate(I_r,J_c), g2[c][r]=gate(J_c,I_r)
    #pragma unroll
    for (int r = 0; r < 4; r++) {
        const int row = i0 + 4 * ty + r;
        const float4 nu = *(const float4*)&noise[(size_t)row * N_NODES + j0 + 4 * tx];
        g1[r][0] = gate_of(nu.x, acc1[r][0], invb);
        g1[r][1] = gate_of(nu.y, acc1[r][1], invb);
        g1[r][2] = gate_of(nu.z, acc1[r][2], invb);
        g1[r][3] = gate_of(nu.w, acc1[r][3], invb);
    }
    #pragma unroll
    for (int c = 0; c < 4; c++) {
        const int row = j0 + 4 * tx + c;
        const float4 nu = *(const float4*)&noise[(size_t)row * N_NODES + i0 + 4 * ty];
        g2[c][0] = gate_of(nu.x, acc2[c][0], invb);
        g2[c][1] = gate_of(nu.y, acc2[c][1], invb);
        g2[c][2] = gate_of(nu.z, acc2[c][2], invb);
        g2[c][3] = gate_of(nu.w, acc2[c][3], invb);
    }
    // m(I_r, J_c) = adj(I_r,J_c) * 0.5*(g1[r][c] + g2[c][r])
    #pragma unroll
    for (int r = 0; r < 4; r++) {
        const int row = i0 + 4 * ty + r;
        const float4 av = *(const float4*)&adj[(size_t)row * N_NODES + j0 + 4 * tx];
        float4 o;
        o.x = av.x * 0.5f * (g1[r][0] + g2[0][r]);
        o.y = av.y * 0.5f * (g1[r][1] + g2[1][r]);
        o.z = av.z * 0.5f * (g1[r][2] + g2[2][r]);
        o.w = av.w * 0.5f * (g1[r][3] + g2[3][r]);
        *(float4*)&g_m[(size_t)row * N_NODES + j0 + 4 * tx] = o;
    }
    // m(J_c, I_r) = adj(J_c,I_r) * same sym value
    #pragma unroll
    for (int c = 0; c < 4; c++) {
        const int row = j0 + 4 * tx + c;
        const float4 av = *(const float4*)&adj[(size_t)row * N_NODES + i0 + 4 * ty];
        float4 o;
        o.x = av.x * 0.5f * (g1[0][c] + g2[c][0]);
        o.y = av.y * 0.5f * (g1[1][c] + g2[c][1]);
        o.z = av.z * 0.5f * (g1[2][c] + g2[c][2]);
        o.w = av.w * 0.5f * (g1[3][c] + g2[c][3]);
        *(float4*)&g_m[(size_t)row * N_NODES + i0 + 4 * ty] = o;
    }
}

// ---------------------------------------------------------------------------
// Kernel 3: pool += sum_rows relu( m @ xw ). 128 blocks x 128 threads,
// 8 rows/block, 4 cols/thread; m rows read via uniform LDG (L2-hot).
// ---------------------------------------------------------------------------
__global__ __launch_bounds__(128) void spmm_kernel()
{
    __shared__ __align__(16) float s_xw[64 * 64];   // xw k-tile (16 KB)
    __shared__ float s_red[8 * 64];

    const int t  = threadIdx.x;
    const int fx = (t & 15) * 4;     // 4 adjacent output cols
    const int rr = t >> 4;           // row 0..7
    const int i0 = blockIdx.x * 8;

    float a0 = 0.f, a1 = 0.f, a2 = 0.f, a3 = 0.f;
    const float4* mrow = (const float4*)&g_m[(size_t)(i0 + rr) * N_NODES];

    for (int k0 = 0; k0 < N_NODES; k0 += 64) {
        __syncthreads();
        #pragma unroll
        for (int p = 0; p < 8; p++) {
            const int idx = (t + p * 128) * 4;
            *(float4*)&s_xw[idx] = *(const float4*)&g_xw[k0 * H_DIM + idx];
        }
        __syncthreads();
        #pragma unroll
        for (int kk = 0; kk < 64; kk += 4) {
            const float4 mv = __ldg(&mrow[(k0 + kk) >> 2]);
            const float4 x0 = *(const float4*)&s_xw[(kk + 0) * 64 + fx];
            const float4 x1 = *(const float4*)&s_xw[(kk + 1) * 64 + fx];
            const float4 x2 = *(const float4*)&s_xw[(kk + 2) * 64 + fx];
            const float4 x3 = *(const float4*)&s_xw[(kk + 3) * 64 + fx];
            a0 = fmaf(mv.x, x0.x, a0); a1 = fmaf(mv.x, x0.y, a1);
            a2 = fmaf(mv.x, x0.z, a2); a3 = fmaf(mv.x, x0.w, a3);
            a0 = fmaf(mv.y, x1.x, a0); a1 = fmaf(mv.y, x1.y, a1);
            a2 = fmaf(mv.y, x1.z, a2); a3 = fmaf(mv.y, x1.w, a3);
            a0 = fmaf(mv.z, x2.x, a0); a1 = fmaf(mv.z, x2.y, a1);
            a2 = fmaf(mv.z, x2.z, a2); a3 = fmaf(mv.z, x2.w, a3);
            a0 = fmaf(mv.w, x3.x, a0); a1 = fmaf(mv.w, x3.y, a1);
            a2 = fmaf(mv.w, x3.z, a2); a3 = fmaf(mv.w, x3.w, a3);
        }
    }
    s_red[rr * 64 + fx + 0] = fmaxf(a0, 0.f);
    s_red[rr * 64 + fx + 1] = fmaxf(a1, 0.f);
    s_red[rr * 64 + fx + 2] = fmaxf(a2, 0.f);
    s_red[rr * 64 + fx + 3] = fmaxf(a3, 0.f);
    __syncthreads();
    if (t < 64) {
        float s = 0.f;
        #pragma unroll
        for (int r = 0; r < 8; r++) s += s_red[r * 64 + t];
        atomicAdd(&g_pool[t], s);
    }
}

// ---------------------------------------------------------------------------
// Kernel 4: logits + softmax on the 64-wide pooled vector.
// ---------------------------------------------------------------------------
__global__ __launch_bounds__(64) void final_kernel(
    const float* __restrict__ Wg2, float* __restrict__ out)
{
    __shared__ float sp[64];
    __shared__ float slog[8];
    __shared__ float sexp[8];

    const int t = threadIdx.x;
    sp[t] = g_pool[t] * (1.0f / (float)N_NODES);
    __syncthreads();
    if (t < N_CLS) {
        float lg = 0.f;
        #pragma unroll 8
        for (int k = 0; k < 64; k++) lg += sp[k] * Wg2[k * N_CLS + t];
        slog[t] = lg;
    }
    __syncthreads();
    if (t < N_CLS) {
        float m = slog[0];
        #pragma unroll
        for (int cc = 1; cc < N_CLS; cc++) m = fmaxf(m, slog[cc]);
        sexp[t] = expf(slog[t] - m);
    }
    __syncthreads();
    if (t < N_CLS) {
        float sum = 0.f;
        #pragma unroll
        for (int cc = 0; cc < N_CLS; cc++) sum += sexp[cc];
        out[t] = sexp[t] / sum;
    }
}

// ---------------------------------------------------------------------------
extern "C" void kernel_launch(void* const* d_in, const int* in_sizes, int n_in,
                              void* d_out, int out_size)
{
    const float* x     = (const float*)d_in[0];
    const float* embed = (const float*)d_in[1];
    const float* adj   = (const float*)d_in[2];
    const float* tmp   = (const float*)d_in[3];
    const float* noise = (const float*)d_in[4];
    // d_in[5] = label (int), unused by the forward pass
    const float* W1    = (const float*)d_in[6];
    const float* b1    = (const float*)d_in[7];
    const float* W2    = (const float*)d_in[8];
    const float* b2    = (const float*)d_in[9];
    const float* Wg1   = (const float*)d_in[10];
    const float* Wg2   = (const float*)d_in[11];
    float* out = (float*)d_out;

    const int edge_smem = (4 * 64 * EPAD + 64) * (int)sizeof(float);  // 69,888 B
    // Idempotent host-side attribute set (no static guard — harness rule).
    cudaFuncSetAttribute(edge_kernel,
                         cudaFuncAttributeMaxDynamicSharedMemorySize,
                         edge_smem);

    prep_kernel<<<128, 64>>>(embed, x, W1, b1, Wg1);
    edge_kernel<<<NBLK * (NBLK + 1) / 2, 256, edge_smem>>>(noise, adj, W2, b2, tmp);
    spmm_kernel<<<128, 128>>>();
    final_kernel<<<1, 64>>>(Wg2, out);
}

// round 6
// speedup vs baseline: 1.1041x; 1.0945x over previous
#include <cuda_runtime.h>
#include <cuda_bf16.h>

#define N_NODES 1024
#define D_EMB 64
#define F_IN 128
#define H_DIM 64
#define N_CLS 8
#define EPAD 68
#define NBLK 16          // 1024/64 node blocks
#define GRID 148         // one block per SM (B200: 148 SMs)
#define THREADS 256

// Scratch (no cudaMalloc allowed)
__device__ float g_a[N_NODES * H_DIM];     // embed @ W1[:64] + b1
__device__ float g_b[N_NODES * H_DIM];     // embed @ W1[64:]
__device__ float g_xw[N_NODES * H_DIM];    // x @ Wg1
__device__ float g_m[N_NODES * N_NODES];   // masked_adj = adj .* sym_mask
__device__ float g_pool[H_DIM];            // sum over nodes of relu(m @ xw)
__device__ unsigned long long g_bar;       // monotonic grid-barrier ticket

// ---------------------------------------------------------------------------
// Device-wide barrier: ticket/generation on a monotonic counter. No reset
// needed between graph replays (generation arithmetic absorbs history), so
// the kernel stays deterministic. Requires all GRID blocks co-resident
// (1 block/SM at 256 threads / 70KB smem -> guaranteed).
// ---------------------------------------------------------------------------
__device__ __forceinline__ void grid_sync()
{
    __syncthreads();
    if (threadIdx.x == 0) {
        __threadfence();
        const unsigned long long ticket = atomicAdd(&g_bar, 1ULL);
        const unsigned long long target =
            (ticket / GRID + 1ULL) * (unsigned long long)GRID;
        while (atomicAdd(&g_bar, 0ULL) < target) { __nanosleep(64); }
        __threadfence();
    }
    __syncthreads();
}

__device__ __forceinline__ float gate_of(float u, float la, float invb)
{
    const float z = (__logf(u) - __logf(1.f - u) + la) * invb;
    return __frcp_rn(1.f + __expf(-z));
}

extern __shared__ float smem[];

__global__ __launch_bounds__(THREADS) void fused_kernel(
    const float* __restrict__ x,     const float* __restrict__ embed,
    const float* __restrict__ adj,   const float* __restrict__ tmp,
    const float* __restrict__ noise, const float* __restrict__ W1,
    const float* __restrict__ b1,    const float* __restrict__ W2,
    const float* __restrict__ b2,    const float* __restrict__ Wg1,
    const float* __restrict__ Wg2,   float* __restrict__ out)
{
    const int t = threadIdx.x;

    // ======================= Phase 0: per-node precompute ===================
    // 128 units of 8 rows. 256 threads: col = t&63, row-group rg = t>>6 (2 rows).
    {
        float* se = smem;              // 8 x 64
        float* sx = smem + 8 * 64;     // 8 x 128

        if (blockIdx.x == 0 && t < H_DIM) g_pool[t] = 0.f;

        const int col = t & 63;
        const int rg  = t >> 6;        // 0..3 -> rows 2rg, 2rg+1

        for (int u = blockIdx.x; u < 128; u += gridDim.x) {
            const int i0 = u * 8;
            __syncthreads();
            #pragma unroll
            for (int p = 0; p < 2; p++)
                se[t + p * 256] = embed[i0 * D_EMB + t + p * 256];
            #pragma unroll
            for (int p = 0; p < 4; p++)
                sx[t + p * 256] = x[i0 * F_IN + t + p * 256];
            __syncthreads();

            const float bias = b1[col];
            float va0 = bias, va1 = bias, vb0 = 0.f, vb1 = 0.f;
            float vx0 = 0.f, vx1 = 0.f;
            const int r0 = rg * 2, r1 = rg * 2 + 1;

            #pragma unroll 4
            for (int k = 0; k < D_EMB; k++) {
                const float w1a = W1[k * H_DIM + col];
                const float w1b = W1[(D_EMB + k) * H_DIM + col];
                const float e0 = se[r0 * D_EMB + k];
                const float e1 = se[r1 * D_EMB + k];
                va0 = fmaf(e0, w1a, va0); va1 = fmaf(e1, w1a, va1);
                vb0 = fmaf(e0, w1b, vb0); vb1 = fmaf(e1, w1b, vb1);
            }
            #pragma unroll 4
            for (int k = 0; k < F_IN; k++) {
                const float wg = Wg1[k * H_DIM + col];
                vx0 = fmaf(sx[r0 * F_IN + k], wg, vx0);
                vx1 = fmaf(sx[r1 * F_IN + k], wg, vx1);
            }
            g_a [(i0 + r0) * H_DIM + col] = va0;
            g_a [(i0 + r1) * H_DIM + col] = va1;
            g_b [(i0 + r0) * H_DIM + col] = vb0;
            g_b [(i0 + r1) * H_DIM + col] = vb1;
            g_xw[(i0 + r0) * H_DIM + col] = vx0;
            g_xw[(i0 + r1) * H_DIM + col] = vx1;
        }
    }
    grid_sync();

    // ================== Phase 1: symmetric edge gate -> g_m =================
    // 136 upper-triangle 64x64 block pairs; one per block (12 blocks idle).
    {
        float* sAi = smem;
        float* sBj = sAi + 64 * EPAD;
        float* sAj = sBj + 64 * EPAD;
        float* sBi = sAj + 64 * EPAD;
        float* sw2 = sBi + 64 * EPAD;

        for (int u = blockIdx.x; u < NBLK * (NBLK + 1) / 2; u += gridDim.x) {
            int b = u, bi = 0;
            while (b >= NBLK - bi) { b -= NBLK - bi; bi++; }
            const int bj = bi + b;
            const int i0 = bi * 64, j0 = bj * 64;

            __syncthreads();
            #pragma unroll
            for (int p = 0; p < 16; p++) {
                const int idx = t + p * 256;
                const int r = idx >> 6, k = idx & 63;
                sAi[k * EPAD + r] = g_a[(i0 + r) * H_DIM + k];
                sBi[k * EPAD + r] = g_b[(i0 + r) * H_DIM + k];
                sAj[k * EPAD + r] = g_a[(j0 + r) * H_DIM + k];
                sBj[k * EPAD + r] = g_b[(j0 + r) * H_DIM + k];
            }
            if (t < 64) sw2[t] = W2[t];
            __syncthreads();

            const int tx = t & 15, ty = t >> 4;
            const float b2s = b2[0];
            float acc1[4][4], acc2[4][4];
            #pragma unroll
            for (int r = 0; r < 4; r++)
                #pragma unroll
                for (int c = 0; c < 4; c++) { acc1[r][c] = b2s; acc2[r][c] = b2s; }

            #pragma unroll 2
            for (int k = 0; k < 64; k++) {
                const float4 ai  = *(const float4*)&sAi[k * EPAD + 4 * ty];
                const float4 bj4 = *(const float4*)&sBj[k * EPAD + 4 * tx];
                const float4 aj  = *(const float4*)&sAj[k * EPAD + 4 * tx];
                const float4 bi4 = *(const float4*)&sBi[k * EPAD + 4 * ty];
                const float w = sw2[k];
                const float av1[4] = {ai.x, ai.y, ai.z, ai.w};
                const float bv1[4] = {bj4.x, bj4.y, bj4.z, bj4.w};
                const float av2[4] = {aj.x, aj.y, aj.z, aj.w};
                const float bv2[4] = {bi4.x, bi4.y, bi4.z, bi4.w};
                #pragma unroll
                for (int r = 0; r < 4; r++)
                    #pragma unroll
                    for (int c = 0; c < 4; c++) {
                        acc1[r][c] = fmaf(fmaxf(av1[r] + bv1[c], 0.f), w, acc1[r][c]);
                        acc2[c][r] = fmaf(fmaxf(av2[c] + bv2[r], 0.f), w, acc2[c][r]);
                    }
            }

            const float invb = __frcp_rn(tmp[0]);
            float g1[4][4], g2[4][4];
            #pragma unroll
            for (int r = 0; r < 4; r++) {
                const int row = i0 + 4 * ty + r;
                const float4 nu = *(const float4*)&noise[(size_t)row * N_NODES + j0 + 4 * tx];
                g1[r][0] = gate_of(nu.x, acc1[r][0], invb);
                g1[r][1] = gate_of(nu.y, acc1[r][1], invb);
                g1[r][2] = gate_of(nu.z, acc1[r][2], invb);
                g1[r][3] = gate_of(nu.w, acc1[r][3], invb);
            }
            #pragma unroll
            for (int c = 0; c < 4; c++) {
                const int row = j0 + 4 * tx + c;
                const float4 nu = *(const float4*)&noise[(size_t)row * N_NODES + i0 + 4 * ty];
                g2[c][0] = gate_of(nu.x, acc2[c][0], invb);
                g2[c][1] = gate_of(nu.y, acc2[c][1], invb);
                g2[c][2] = gate_of(nu.z, acc2[c][2], invb);
                g2[c][3] = gate_of(nu.w, acc2[c][3], invb);
            }
            #pragma unroll
            for (int r = 0; r < 4; r++) {
                const int row = i0 + 4 * ty + r;
                const float4 av = *(const float4*)&adj[(size_t)row * N_NODES + j0 + 4 * tx];
                float4 o;
                o.x = av.x * 0.5f * (g1[r][0] + g2[0][r]);
                o.y = av.y * 0.5f * (g1[r][1] + g2[1][r]);
                o.z = av.z * 0.5f * (g1[r][2] + g2[2][r]);
                o.w = av.w * 0.5f * (g1[r][3] + g2[3][r]);
                *(float4*)&g_m[(size_t)row * N_NODES + j0 + 4 * tx] = o;
            }
            #pragma unroll
            for (int c = 0; c < 4; c++) {
                const int row = j0 + 4 * tx + c;
                const float4 av = *(const float4*)&adj[(size_t)row * N_NODES + i0 + 4 * ty];
                float4 o;
                o.x = av.x * 0.5f * (g1[0][c] + g2[c][0]);
                o.y = av.y * 0.5f * (g1[1][c] + g2[c][1]);
                o.z = av.z * 0.5f * (g1[2][c] + g2[c][2]);
                o.w = av.w * 0.5f * (g1[3][c] + g2[c][3]);
                *(float4*)&g_m[(size_t)row * N_NODES + i0 + 4 * ty] = o;
            }
        }
    }
    grid_sync();

    // =============== Phase 2: pool += sum_rows relu(m @ xw) =================
    // 128 units of 8 rows; 256 threads: rr = t>>5 (warp-uniform), 2 cols each.
    {
        float* s_xw  = smem;            // 64 x 64
        float* s_red = smem + 64 * 64;  // 8 x 64

        const int fx = (t & 31) * 2;
        const int rr = t >> 5;

        for (int u = blockIdx.x; u < 128; u += gridDim.x) {
            const int i0 = u * 8;
            float a0 = 0.f, a1 = 0.f;
            const float4* mrow = (const float4*)&g_m[(size_t)(i0 + rr) * N_NODES];

            for (int k0 = 0; k0 < N_NODES; k0 += 64) {
                __syncthreads();
                #pragma unroll
                for (int p = 0; p < 4; p++) {
                    const int idx = (t + p * 256) * 4;
                    *(float4*)&s_xw[idx] = *(const float4*)&g_xw[k0 * H_DIM + idx];
                }
                __syncthreads();
                #pragma unroll
                for (int kk = 0; kk < 64; kk += 4) {
                    const float4 mv = __ldg(&mrow[(k0 + kk) >> 2]);
                    const float2 x0 = *(const float2*)&s_xw[(kk + 0) * 64 + fx];
                    const float2 x1 = *(const float2*)&s_xw[(kk + 1) * 64 + fx];
                    const float2 x2 = *(const float2*)&s_xw[(kk + 2) * 64 + fx];
                    const float2 x3 = *(const float2*)&s_xw[(kk + 3) * 64 + fx];
                    a0 = fmaf(mv.x, x0.x, a0); a1 = fmaf(mv.x, x0.y, a1);
                    a0 = fmaf(mv.y, x1.x, a0); a1 = fmaf(mv.y, x1.y, a1);
                    a0 = fmaf(mv.z, x2.x, a0); a1 = fmaf(mv.z, x2.y, a1);
                    a0 = fmaf(mv.w, x3.x, a0); a1 = fmaf(mv.w, x3.y, a1);
                }
            }
            s_red[rr * 64 + fx]     = fmaxf(a0, 0.f);
            s_red[rr * 64 + fx + 1] = fmaxf(a1, 0.f);
            __syncthreads();
            if (t < 64) {
                float s = 0.f;
                #pragma unroll
                for (int r = 0; r < 8; r++) s += s_red[r * 64 + t];
                atomicAdd(&g_pool[t], s);
            }
            __syncthreads();
        }
    }
    grid_sync();

    // ================= Phase 3: logits + softmax (block 0) ==================
    if (blockIdx.x == 0) {
        float* sp   = smem;
        float* slog = smem + 64;
        float* sexp = smem + 72;

        if (t < 64) sp[t] = g_pool[t] * (1.0f / (float)N_NODES);
        __syncthreads();
        if (t < N_CLS) {
            float lg = 0.f;
            #pragma unroll 8
            for (int k = 0; k < 64; k++) lg += sp[k] * Wg2[k * N_CLS + t];
            slog[t] = lg;
        }
        __syncthreads();
        if (t < N_CLS) {
            float m = slog[0];
            #pragma unroll
            for (int cc = 1; cc < N_CLS; cc++) m = fmaxf(m, slog[cc]);
            sexp[t] = expf(slog[t] - m);
        }
        __syncthreads();
        if (t < N_CLS) {
            float sum = 0.f;
            #pragma unroll
            for (int cc = 0; cc < N_CLS; cc++) sum += sexp[cc];
            out[t] = sexp[t] / sum;
        }
    }
}

// ---------------------------------------------------------------------------
extern "C" void kernel_launch(void* const* d_in, const int* in_sizes, int n_in,
                              void* d_out, int out_size)
{
    const float* x     = (const float*)d_in[0];
    const float* embed = (const float*)d_in[1];
    const float* adj   = (const float*)d_in[2];
    const float* tmp   = (const float*)d_in[3];
    const float* noise = (const float*)d_in[4];
    // d_in[5] = label (int), unused by the forward pass
    const float* W1    = (const float*)d_in[6];
    const float* b1    = (const float*)d_in[7];
    const float* W2    = (const float*)d_in[8];
    const float* b2    = (const float*)d_in[9];
    const float* Wg1   = (const float*)d_in[10];
    const float* Wg2   = (const float*)d_in[11];
    float* out = (float*)d_out;

    const int smem_bytes = (4 * 64 * EPAD + 64) * (int)sizeof(float); // 69,888 B
    cudaFuncSetAttribute(fused_kernel,
                         cudaFuncAttributeMaxDynamicSharedMemorySize,
                         smem_bytes);

    fused_kernel<<<GRID, THREADS, smem_bytes>>>(
        x, embed, adj, tmp, noise, W1, b1, W2, b2, Wg1, Wg2, out);
}